// round 15
// baseline (speedup 1.0000x reference)
#include <cuda_runtime.h>

#define HID 50
#define NPTS 8192
#define NPARA 5000
#define WARPS_PER_BLOCK 8
#define THREADS (WARPS_PER_BLOCK * 32)
#define NBLOCKS 296                      // exactly 2 CTAs per SM on 148 SMs

#define N4TASKS 1664                     // 4-pt tasks: points 0..6655
#define N2TASKS 768                      // 2-pt tail:  points 6656..8191
#define NTASKS_ALL (N4TASKS + N2TASKS)   // 2432
#define PTS4 (N4TASKS * 4)               // 6656

// shared layout (floats)
#define OFF_WIN 0
#define OFF_BIN 150
#define OFF_WH  200
#define OFF_BH  10200
#define OFF_WO  10400
#define OFF_BO  10500
#define OFF_STATE 10504                  // byte 42016, 16B aligned
#define ST_STRIDE 1200                   // per warp: 50 units x 24 floats (P=4 max)
#define OFF_OUT (OFF_STATE + WARPS_PER_BLOCK * ST_STRIDE)   // 20104
#define OFF_PART (OFF_OUT + WARPS_PER_BLOCK * 32)           // 20360, 8 warps x 4 slots x 6
#define SMEM_FLOATS (OFF_PART + WARPS_PER_BLOCK * 24)       // 20552
#define SMEM_BYTES (SMEM_FLOATS * 4)     // 82208 B -> 2 CTAs/SM (164KB)

typedef unsigned long long u64;

__device__ double g_sums[6];             // zero-init at load; reset after finalize
__device__ unsigned int g_next;          // task queue; reset after finalize

__device__ __forceinline__ u64 pack2(float lo, float hi) {
    u64 r; asm("mov.b64 %0, {%1, %2};" : "=l"(r) : "f"(lo), "f"(hi)); return r;
}
__device__ __forceinline__ void unpack2(u64 v, float& lo, float& hi) {
    asm("mov.b64 {%0, %1}, %2;" : "=f"(lo), "=f"(hi) : "l"(v));
}
// d.lo += a.lo*b.lo ; d.hi += a.hi*b.hi   (SASS FFMA2, PTX-only)
__device__ __forceinline__ void ffma2(u64& d, u64 a, u64 b) {
    asm("fma.rn.f32x2 %0, %1, %2, %0;" : "+l"(d) : "l"(a), "l"(b));
}

// tanh(z) and sech^2(z): r = 1/(e^{2z}+1); h = 1-2r; 1-h^2 = 4r(1-r)
__device__ __forceinline__ void tanh_s(float z, float& h, float& s) {
    float e = __expf(2.0f * z);
    float r = __fdividef(1.0f, e + 1.0f);
    h = 1.0f - 2.0f * r;
    s = 4.0f * r * (1.0f - r);
}

// Process one task of P points (P = 4 or 2). State layout per unit: [ch 6][pt P].
template <int P>
__device__ __forceinline__ void do_task(
    int p0, const float* __restrict__ x,
    float* __restrict__ sm, float* __restrict__ st,
    int lane, int warp)
{
    constexpr int US = 6 * P;            // floats per unit
    const int j1 = lane;
    const int j2 = lane + 32;
    const bool has2 = (j2 < HID);

    // hoist point coords
    float xv[P][3];
    #pragma unroll
    for (int p = 0; p < P; p++) {
        xv[p][0] = x[(p0 + p) * 3 + 0];
        xv[p][1] = x[(p0 + p) * 3 + 1];
        xv[p][2] = x[(p0 + p) * 3 + 2];
    }
    __syncwarp();   // prior task's reads of st/out done before overwrite

    // ---- input layer
    #pragma unroll
    for (int o = 0; o < 2; o++) {
        int j = lane + 32 * o;
        if (j < HID) {
            float w0 = sm[OFF_WIN + j];
            float w1 = sm[OFF_WIN + 50 + j];
            float w2 = sm[OFF_WIN + 100 + j];
            float bj = sm[OFF_BIN + j];
            float h_[P], d0_[P], dd0_[P], d1_[P], dd1_[P], d2_[P];
            #pragma unroll
            for (int p = 0; p < P; p++) {
                float z = bj + xv[p][0] * w0 + xv[p][1] * w1 + xv[p][2] * w2;
                float h, s; tanh_s(z, h, s);
                h_[p] = h;
                d0_[p] = s * w0;  dd0_[p] = -2.0f * h * d0_[p] * w0;
                d1_[p] = s * w1;  dd1_[p] = -2.0f * h * d1_[p] * w1;
                d2_[p] = s * w2;
            }
            float* u = st + j * US;
            if constexpr (P == 4) {
                ((float4*)u)[0] = make_float4(h_[0], h_[1], h_[2], h_[3]);
                ((float4*)u)[1] = make_float4(d0_[0], d0_[1], d0_[2], d0_[3]);
                ((float4*)u)[2] = make_float4(dd0_[0], dd0_[1], dd0_[2], dd0_[3]);
                ((float4*)u)[3] = make_float4(d1_[0], d1_[1], d1_[2], d1_[3]);
                ((float4*)u)[4] = make_float4(dd1_[0], dd1_[1], dd1_[2], dd1_[3]);
                ((float4*)u)[5] = make_float4(d2_[0], d2_[1], d2_[2], d2_[3]);
            } else {
                ((float2*)u)[0] = make_float2(h_[0], h_[1]);
                ((float2*)u)[1] = make_float2(d0_[0], d0_[1]);
                ((float2*)u)[2] = make_float2(dd0_[0], dd0_[1]);
                ((float2*)u)[3] = make_float2(d1_[0], d1_[1]);
                ((float2*)u)[4] = make_float2(dd1_[0], dd1_[1]);
                ((float2*)u)[5] = make_float2(d2_[0], d2_[1]);
            }
        }
    }
    __syncwarp();

    // ---- 4 hidden layers
    for (int l = 0; l < 4; l++) {
        const float* Wl = sm + OFF_WH + l * 2500;
        const float* bl = sm + OFF_BH + l * 50;
        float b1 = bl[j1], b2 = has2 ? bl[j2] : 0.0f;
        u64 bb1 = pack2(b1, b1), bb2 = pack2(b2, b2);

        u64 acc[6][2][P / 2];
        #pragma unroll
        for (int c = 0; c < 6; c++)
            #pragma unroll
            for (int pr = 0; pr < P / 2; pr++) {
                acc[c][0][pr] = (c == 0) ? bb1 : 0ull;
                acc[c][1][pr] = (c == 0) ? bb2 : 0ull;
            }

        #pragma unroll
        for (int k = 0; k < HID; k++) {
            float w1 = Wl[k * 50 + j1];
            float w2 = has2 ? Wl[k * 50 + j2] : 0.0f;
            u64 ww1 = pack2(w1, w1);
            u64 ww2 = pack2(w2, w2);
            if constexpr (P == 4) {
                const ulonglong2* sp = (const ulonglong2*)(st + k * US);
                #pragma unroll
                for (int c = 0; c < 6; c++) {
                    ulonglong2 v = sp[c];            // LDS.128 bcast: {p0,p1},{p2,p3}
                    ffma2(acc[c][0][0], v.x, ww1); ffma2(acc[c][1][0], v.x, ww2);
                    ffma2(acc[c][0][1], v.y, ww1); ffma2(acc[c][1][1], v.y, ww2);
                }
            } else {
                const u64* sp = (const u64*)(st + k * US);
                #pragma unroll
                for (int c = 0; c < 6; c++) {
                    u64 v = sp[c];                   // LDS.64 bcast: {p0,p1}
                    ffma2(acc[c][0][0], v, ww1); ffma2(acc[c][1][0], v, ww2);
                }
            }
        }
        __syncwarp();   // all reads of old state complete before overwrite

        #pragma unroll
        for (int jj = 0; jj < 2; jj++) {
            if (jj == 0 || has2) {
                float h_[P], d0_[P], dd0_[P], d1_[P], dd1_[P], d2_[P];
                #pragma unroll
                for (int p = 0; p < P; p++) {
                    const int pr = p / 2;
                    float lo, hi;
                    float z, zx, zxx, zy, zyy, zt;
                    unpack2(acc[0][jj][pr], lo, hi); z   = (p & 1) ? hi : lo;
                    unpack2(acc[1][jj][pr], lo, hi); zx  = (p & 1) ? hi : lo;
                    unpack2(acc[2][jj][pr], lo, hi); zxx = (p & 1) ? hi : lo;
                    unpack2(acc[3][jj][pr], lo, hi); zy  = (p & 1) ? hi : lo;
                    unpack2(acc[4][jj][pr], lo, hi); zyy = (p & 1) ? hi : lo;
                    unpack2(acc[5][jj][pr], lo, hi); zt  = (p & 1) ? hi : lo;
                    float h, s; tanh_s(z, h, s);
                    h_[p] = h;
                    d0_[p] = s * zx;  dd0_[p] = fmaf(-2.0f * h * d0_[p], zx, s * zxx);
                    d1_[p] = s * zy;  dd1_[p] = fmaf(-2.0f * h * d1_[p], zy, s * zyy);
                    d2_[p] = s * zt;
                }
                float* u = st + (jj ? j2 : j1) * US;
                if constexpr (P == 4) {
                    ((float4*)u)[0] = make_float4(h_[0], h_[1], h_[2], h_[3]);
                    ((float4*)u)[1] = make_float4(d0_[0], d0_[1], d0_[2], d0_[3]);
                    ((float4*)u)[2] = make_float4(dd0_[0], dd0_[1], dd0_[2], dd0_[3]);
                    ((float4*)u)[3] = make_float4(d1_[0], d1_[1], d1_[2], d1_[3]);
                    ((float4*)u)[4] = make_float4(dd1_[0], dd1_[1], dd1_[2], dd1_[3]);
                    ((float4*)u)[5] = make_float4(d2_[0], d2_[1], d2_[2], d2_[3]);
                } else {
                    ((float2*)u)[0] = make_float2(h_[0], h_[1]);
                    ((float2*)u)[1] = make_float2(d0_[0], d0_[1]);
                    ((float2*)u)[2] = make_float2(dd0_[0], dd0_[1]);
                    ((float2*)u)[3] = make_float2(d1_[0], d1_[1]);
                    ((float2*)u)[4] = make_float2(dd1_[0], dd1_[1]);
                    ((float2*)u)[5] = make_float2(d2_[0], d2_[1]);
                }
            }
        }
        __syncwarp();
    }

    // ---- output layer: lane = pt*8 + (cidx*2 + o); channels {val,dxx,dyy,dt}
    {
        int pt = lane >> 3;
        int l8 = lane & 7;
        if (pt < P) {
            int cidx = l8 >> 1;
            int o = l8 & 1;
            int c = (cidx == 0) ? 0 : (cidx == 1) ? 2 : (cidx == 2) ? 4 : 5;
            const float* cp = st + c * P + pt;
            float acc0 = (cidx == 0) ? sm[OFF_BO + o] : 0.0f;
            float acc1 = 0.0f;
            #pragma unroll
            for (int k = 0; k < HID; k += 2) {
                acc0 = fmaf(cp[k * US],       sm[OFF_WO + k * 2 + o],       acc0);
                acc1 = fmaf(cp[(k + 1) * US], sm[OFF_WO + (k + 1) * 2 + o], acc1);
            }
            sm[OFF_OUT + warp * 32 + pt * 8 + l8] = acc0 + acc1;
        }
    }
    __syncwarp();

    if (lane < P) {
        const float* o8 = sm + OFF_OUT + warp * 32 + lane * 8;
        float u   = o8[0], v   = o8[1];
        float uxx = o8[2], vxx = o8[3];
        float uyy = o8[4], vyy = o8[5];
        float ut  = o8[6], vt  = o8[7];
        float Q  = u * u + v * v;
        float A1 = vt - 0.5f * uxx - 0.5f * vyy - Q * u + v;
        float A2 = ut + 0.5f * vxx - 0.5f * uyy + Q * v + u;
        float B1 = uyy, B2 = vyy;
        float C1 = Q * v, C2 = Q * u;
        float* pp = sm + OFF_PART + (warp * 4 + lane) * 6;
        pp[0] += A1 * A1 + A2 * A2;
        pp[1] += B1 * B1 + B2 * B2;
        pp[2] += C1 * C1 + C2 * C2;
        pp[3] += A2 * B2 - A1 * B1;
        pp[4] += A1 * C1 + A2 * C2;
        pp[5] += B1 * C1 - B2 * C2;
    }
}

__global__ void __launch_bounds__(THREADS, 2) pinn_kernel(
    const float* __restrict__ x,
    const float* __restrict__ W_in, const float* __restrict__ b_in,
    const float* __restrict__ W_hid, const float* __restrict__ b_hid,
    const float* __restrict__ W_out, const float* __restrict__ b_out)
{
    extern __shared__ float sm[];
    const int tid = threadIdx.x;

    for (int i = tid; i < 2500; i += THREADS)
        ((float4*)(sm + OFF_WH))[i] = ((const float4*)W_hid)[i];
    for (int i = tid; i < 150;  i += THREADS) sm[OFF_WIN + i] = W_in[i];
    for (int i = tid; i < 50;   i += THREADS) sm[OFF_BIN + i] = b_in[i];
    for (int i = tid; i < 200;  i += THREADS) sm[OFF_BH  + i] = b_hid[i];
    for (int i = tid; i < 100;  i += THREADS) sm[OFF_WO  + i] = W_out[i];
    if (tid < 2) sm[OFF_BO + tid] = b_out[tid];
    for (int i = tid; i < WARPS_PER_BLOCK * 24; i += THREADS)
        sm[OFF_PART + i] = 0.0f;        // per-warp residual accumulators
    __syncthreads();

    const int warp = tid >> 5;
    const int lane = tid & 31;
    float* st = sm + OFF_STATE + warp * ST_STRIDE;

    // ---- dynamic queue: 4pt tasks first (LPT), then the 2pt tail
    while (true) {
        unsigned id = 0;
        if (lane == 0) id = atomicAdd(&g_next, 1u);
        id = __shfl_sync(0xffffffffu, id, 0);
        if (id >= (unsigned)NTASKS_ALL) break;
        if (id < (unsigned)N4TASKS)
            do_task<4>((int)id * 4, x, sm, st, lane, warp);
        else
            do_task<2>(PTS4 + ((int)id - N4TASKS) * 2, x, sm, st, lane, warp);
    }
    __syncthreads();

    if (tid < 6) {
        double s = 0.0;
        #pragma unroll
        for (int w = 0; w < WARPS_PER_BLOCK * 4; w++)
            s += (double)sm[OFF_PART + w * 6 + tid];
        atomicAdd(&g_sums[tid], s);
    }
}

__global__ void finalize_kernel(const float* __restrict__ para, float* __restrict__ out) {
    int p = blockIdx.x * blockDim.x + threadIdx.x;
    if (p < NPARA) {
        double a = (double)para[p * 3 + 0];
        double c = (double)para[p * 3 + 2];
        double r = g_sums[0]
                 + 0.25 * a * a * g_sums[1]
                 + c * c * g_sums[2]
                 + a * g_sums[3]
                 - 2.0 * c * g_sums[4]
                 + a * c * g_sums[5];
        out[p] = (float)(r * (1.0 / (double)NPTS));
    }
}

__global__ void reset_kernel() {
    if (threadIdx.x < 6) g_sums[threadIdx.x] = 0.0;
    if (threadIdx.x == 0) g_next = 0u;
}

extern "C" void kernel_launch(void* const* d_in, const int* in_sizes, int n_in,
                              void* d_out, int out_size) {
    const float* x     = (const float*)d_in[0];
    const float* para  = (const float*)d_in[1];
    const float* W_in  = (const float*)d_in[2];
    const float* b_in  = (const float*)d_in[3];
    const float* W_hid = (const float*)d_in[4];
    const float* b_hid = (const float*)d_in[5];
    const float* W_out = (const float*)d_in[6];
    const float* b_out = (const float*)d_in[7];
    float* out = (float*)d_out;

    cudaFuncSetAttribute(pinn_kernel, cudaFuncAttributeMaxDynamicSharedMemorySize, SMEM_BYTES);
    pinn_kernel<<<NBLOCKS, THREADS, SMEM_BYTES>>>(
        x, W_in, b_in, W_hid, b_hid, W_out, b_out);
    finalize_kernel<<<(NPARA + 255) / 256, 256>>>(para, out);
    reset_kernel<<<1, 32>>>();
}

// round 16
// speedup vs baseline: 1.2992x; 1.2992x over previous
#include <cuda_runtime.h>
#include <cstdint>

#define HID 50
#define NPTS 8192
#define NPARA 5000
#define G 32                         // points per CTA
#define RROWS (6 * G)                // 192 state rows: r = pt*6 + ch
#define STRIDE 57                    // smem row stride (floats)
#define NBLK (NPTS / G)              // 256 CTAs
#define THREADS 384                  // 12 warps; warp w owns m-tile w (16 rows)

// shared layout (floats)
#define OFF_S    0                   // state/Z buffer [192][57] = 10944
#define OFF_WH   10944               // 4 x 50 x 50, tf32-rounded
#define OFF_WIN  20944               // 3 x 50
#define OFF_BIN  21094
#define OFF_BH   21144               // 4 x 50
#define OFF_WO   21344               // 50 x 2
#define OFF_BO   21444               // 2 (pad 4)
#define OFF_X    21448               // 32 pts x 3
#define OFF_OUT8 21544               // 32 x 8
#define OFF_PART 21800               // 32 x 6
#define SMEM_FLOATS 21992
#define SMEM_BYTES (SMEM_FLOATS * 4) // 87968 B -> 2 CTAs/SM, all 256 resident

__device__ double g_sums[6];         // zero-init at load; reset after finalize

__device__ __forceinline__ float tf32r(float v) {
    uint32_t u;
    asm("cvt.rna.tf32.f32 %0, %1;" : "=r"(u) : "f"(v));
    return __uint_as_float(u);
}

// tanh(z) and sech^2(z): r = 1/(e^{2z}+1); h = 1-2r; 1-h^2 = 4r(1-r)
__device__ __forceinline__ void tanh_s(float z, float& h, float& s) {
    float e = __expf(2.0f * z);
    float r = __fdividef(1.0f, e + 1.0f);
    h = 1.0f - 2.0f * r;
    s = 4.0f * r * (1.0f - r);
}

// m16n8k8 tf32 mma, fp32 accumulate
__device__ __forceinline__ void mma_tf32(float& c0, float& c1, float& c2, float& c3,
                                         uint32_t a0, uint32_t a1, uint32_t a2, uint32_t a3,
                                         uint32_t b0, uint32_t b1) {
    asm volatile(
        "mma.sync.aligned.m16n8k8.row.col.f32.tf32.tf32.f32 "
        "{%0,%1,%2,%3}, {%4,%5,%6,%7}, {%8,%9}, {%0,%1,%2,%3};"
        : "+f"(c0), "+f"(c1), "+f"(c2), "+f"(c3)
        : "r"(a0), "r"(a1), "r"(a2), "r"(a3), "r"(b0), "r"(b1));
}

__global__ void __launch_bounds__(THREADS, 2) pinn_kernel(
    const float* __restrict__ x,
    const float* __restrict__ W_in, const float* __restrict__ b_in,
    const float* __restrict__ W_hid, const float* __restrict__ b_hid,
    const float* __restrict__ W_out, const float* __restrict__ b_out)
{
    extern __shared__ float sm[];
    const int tid = threadIdx.x;
    const int p0 = blockIdx.x * G;

    // ---- prologue: weights (W_hid tf32-rounded once), x slice
    for (int i = tid; i < 10000; i += THREADS) sm[OFF_WH + i] = tf32r(W_hid[i]);
    for (int i = tid; i < 150;   i += THREADS) sm[OFF_WIN + i] = W_in[i];
    for (int i = tid; i < 50;    i += THREADS) sm[OFF_BIN + i] = b_in[i];
    for (int i = tid; i < 200;   i += THREADS) sm[OFF_BH  + i] = b_hid[i];
    for (int i = tid; i < 100;   i += THREADS) sm[OFF_WO  + i] = W_out[i];
    if (tid < 2) sm[OFF_BO + tid] = b_out[tid];
    for (int i = tid; i < G * 3; i += THREADS) sm[OFF_X + i] = x[p0 * 3 + i];
    __syncthreads();

    const int lane = tid & 31;
    const int warp = tid >> 5;
    const int gq = lane >> 2;        // mma groupID (0..7)
    const int tq = lane & 3;         // mma threadID_in_group (0..3)

    // ---- input layer: (pt, j) over 32x50; rows r = pt*6+ch, tf32-rounded state
    for (int idx = tid; idx < G * HID; idx += THREADS) {
        int pt = idx / HID, j = idx - pt * HID;
        float x0 = sm[OFF_X + pt * 3 + 0];
        float x1 = sm[OFF_X + pt * 3 + 1];
        float x2 = sm[OFF_X + pt * 3 + 2];
        float w0 = sm[OFF_WIN + j], w1 = sm[OFF_WIN + 50 + j], w2 = sm[OFF_WIN + 100 + j];
        float z = sm[OFF_BIN + j] + x0 * w0 + x1 * w1 + x2 * w2;
        float h, s; tanh_s(z, h, s);
        float d0 = s * w0, dd0 = -2.0f * h * d0 * w0;
        float d1 = s * w1, dd1 = -2.0f * h * d1 * w1;
        float d2 = s * w2;
        int base = (pt * 6) * STRIDE + j;
        sm[OFF_S + base + 0 * STRIDE] = tf32r(h);
        sm[OFF_S + base + 1 * STRIDE] = tf32r(d0);
        sm[OFF_S + base + 2 * STRIDE] = tf32r(dd0);
        sm[OFF_S + base + 3 * STRIDE] = tf32r(d1);
        sm[OFF_S + base + 4 * STRIDE] = tf32r(dd1);
        sm[OFF_S + base + 5 * STRIDE] = tf32r(d2);
    }
    __syncthreads();

    const int row0 = warp * 16 + gq;   // a0/a2, c0/c1 row
    const int row1 = row0 + 8;         // a1/a3, c2/c3 row
    const int ch0 = row0 % 6;          // channel of row0 (bias only on ch==0)
    const int ch1 = row1 % 6;

    // ---- 4 hidden layers: Z[192,50] = S[192,50] @ W[50,50] (+bias on ch0 rows)
    for (int l = 0; l < 4; l++) {
        const float* Wl = sm + OFF_WH + l * 2500;
        const float* bl = sm + OFF_BH + l * 50;

        // C init: bias on value-channel rows only
        float C[7][4];
        #pragma unroll
        for (int n = 0; n < 7; n++) {
            int col0 = n * 8 + tq * 2, col1 = col0 + 1;
            C[n][0] = (ch0 == 0 && col0 < HID) ? bl[col0] : 0.0f;
            C[n][1] = (ch0 == 0 && col1 < HID) ? bl[col1] : 0.0f;
            C[n][2] = (ch1 == 0 && col0 < HID) ? bl[col0] : 0.0f;
            C[n][3] = (ch1 == 0 && col1 < HID) ? bl[col1] : 0.0f;
        }

        // two k-half passes to bound A-frag registers
        #pragma unroll
        for (int half = 0; half < 2; half++) {
            const int s0 = half * 4;
            const int ns = half ? 3 : 4;          // ksteps 0-3, then 4-6
            uint32_t A[4][4];
            #pragma unroll
            for (int ss = 0; ss < 4; ss++) {
                if (ss < ns) {
                    int ka = (s0 + ss) * 8 + tq;       // cols for a0/a1
                    int kb = ka + 4;                   // cols for a2/a3
                    float v0 = (ka < HID) ? sm[OFF_S + row0 * STRIDE + ka] : 0.0f;
                    float v1 = (ka < HID) ? sm[OFF_S + row1 * STRIDE + ka] : 0.0f;
                    float v2 = (kb < HID) ? sm[OFF_S + row0 * STRIDE + kb] : 0.0f;
                    float v3 = (kb < HID) ? sm[OFF_S + row1 * STRIDE + kb] : 0.0f;
                    A[ss][0] = __float_as_uint(v0);
                    A[ss][1] = __float_as_uint(v1);
                    A[ss][2] = __float_as_uint(v2);
                    A[ss][3] = __float_as_uint(v3);
                }
            }
            #pragma unroll
            for (int n = 0; n < 7; n++) {
                int nn = n * 8 + gq;                   // B col (n-dim)
                #pragma unroll
                for (int ss = 0; ss < 4; ss++) {
                    if (ss < ns) {
                        int k0 = (s0 + ss) * 8 + tq;   // B rows (k-dim)
                        int k1 = k0 + 4;
                        float wb0 = (k0 < HID && nn < HID) ? Wl[k0 * HID + nn] : 0.0f;
                        float wb1 = (k1 < HID && nn < HID) ? Wl[k1 * HID + nn] : 0.0f;
                        mma_tf32(C[n][0], C[n][1], C[n][2], C[n][3],
                                 A[ss][0], A[ss][1], A[ss][2], A[ss][3],
                                 __float_as_uint(wb0), __float_as_uint(wb1));
                    }
                }
            }
        }
        __syncthreads();   // all warps done reading S before overwrite

        // store raw Z in place (cols up to 55 < STRIDE, junk cols never read)
        #pragma unroll
        for (int n = 0; n < 7; n++) {
            int col0 = n * 8 + tq * 2;
            sm[OFF_S + row0 * STRIDE + col0]     = C[n][0];
            sm[OFF_S + row0 * STRIDE + col0 + 1] = C[n][1];
            sm[OFF_S + row1 * STRIDE + col0]     = C[n][2];
            sm[OFF_S + row1 * STRIDE + col0 + 1] = C[n][3];
        }
        __syncthreads();

        // elementwise tanh/chain transform, in place (each thread owns its 6 slots)
        for (int idx = tid; idx < G * HID; idx += THREADS) {
            int pt = idx / HID, col = idx - pt * HID;
            int base = OFF_S + (pt * 6) * STRIDE + col;
            float z   = sm[base + 0 * STRIDE];
            float zx  = sm[base + 1 * STRIDE];
            float zxx = sm[base + 2 * STRIDE];
            float zy  = sm[base + 3 * STRIDE];
            float zyy = sm[base + 4 * STRIDE];
            float zt  = sm[base + 5 * STRIDE];
            float h, s; tanh_s(z, h, s);
            float d0  = s * zx;
            float dd0 = fmaf(-2.0f * h * d0, zx, s * zxx);
            float d1  = s * zy;
            float dd1 = fmaf(-2.0f * h * d1, zy, s * zyy);
            float d2  = s * zt;
            sm[base + 0 * STRIDE] = tf32r(h);
            sm[base + 1 * STRIDE] = tf32r(d0);
            sm[base + 2 * STRIDE] = tf32r(dd0);
            sm[base + 3 * STRIDE] = tf32r(d1);
            sm[base + 4 * STRIDE] = tf32r(dd1);
            sm[base + 5 * STRIDE] = tf32r(d2);
        }
        __syncthreads();
    }

    // ---- output layer: 8 dots per point (channels {val,dxx,dyy,dt} x {u,v})
    if (tid < G * 8) {
        int pt = tid >> 3, q = tid & 7;
        int cidx = q >> 1, o = q & 1;
        int ch = (cidx == 0) ? 0 : (cidx == 1) ? 2 : (cidx == 2) ? 4 : 5;
        const float* cp = sm + OFF_S + (pt * 6 + ch) * STRIDE;
        float acc = (cidx == 0) ? sm[OFF_BO + o] : 0.0f;
        #pragma unroll 2
        for (int k = 0; k < HID; k++)
            acc = fmaf(cp[k], sm[OFF_WO + k * 2 + o], acc);
        sm[OFF_OUT8 + pt * 8 + q] = acc;
    }
    __syncthreads();

    if (tid < G) {
        const float* o8 = sm + OFF_OUT8 + tid * 8;
        float u   = o8[0], v   = o8[1];
        float uxx = o8[2], vxx = o8[3];
        float uyy = o8[4], vyy = o8[5];
        float ut  = o8[6], vt  = o8[7];
        float Q  = u * u + v * v;
        float A1 = vt - 0.5f * uxx - 0.5f * vyy - Q * u + v;
        float A2 = ut + 0.5f * vxx - 0.5f * uyy + Q * v + u;
        float B1 = uyy, B2 = vyy;
        float C1 = Q * v, C2 = Q * u;
        float* pp = sm + OFF_PART + tid * 6;
        pp[0] = A1 * A1 + A2 * A2;
        pp[1] = B1 * B1 + B2 * B2;
        pp[2] = C1 * C1 + C2 * C2;
        pp[3] = A2 * B2 - A1 * B1;
        pp[4] = A1 * C1 + A2 * C2;
        pp[5] = B1 * C1 - B2 * C2;
    }
    __syncthreads();

    if (tid < 6) {
        double s = 0.0;
        #pragma unroll
        for (int p = 0; p < G; p++)
            s += (double)sm[OFF_PART + p * 6 + tid];
        atomicAdd(&g_sums[tid], s);
    }
}

__global__ void finalize_kernel(const float* __restrict__ para, float* __restrict__ out) {
    int p = blockIdx.x * blockDim.x + threadIdx.x;
    if (p < NPARA) {
        double a = (double)para[p * 3 + 0];
        double c = (double)para[p * 3 + 2];
        double r = g_sums[0]
                 + 0.25 * a * a * g_sums[1]
                 + c * c * g_sums[2]
                 + a * g_sums[3]
                 - 2.0 * c * g_sums[4]
                 + a * c * g_sums[5];
        out[p] = (float)(r * (1.0 / (double)NPTS));
    }
}

__global__ void reset_kernel() {
    if (threadIdx.x < 6) g_sums[threadIdx.x] = 0.0;
}

extern "C" void kernel_launch(void* const* d_in, const int* in_sizes, int n_in,
                              void* d_out, int out_size) {
    const float* x     = (const float*)d_in[0];
    const float* para  = (const float*)d_in[1];
    const float* W_in  = (const float*)d_in[2];
    const float* b_in  = (const float*)d_in[3];
    const float* W_hid = (const float*)d_in[4];
    const float* b_hid = (const float*)d_in[5];
    const float* W_out = (const float*)d_in[6];
    const float* b_out = (const float*)d_in[7];
    float* out = (float*)d_out;

    cudaFuncSetAttribute(pinn_kernel, cudaFuncAttributeMaxDynamicSharedMemorySize, SMEM_BYTES);
    pinn_kernel<<<NBLK, THREADS, SMEM_BYTES>>>(
        x, W_in, b_in, W_hid, b_hid, W_out, b_out);
    finalize_kernel<<<(NPARA + 255) / 256, 256>>>(para, out);
    reset_kernel<<<1, 32>>>();
}